// round 3
// baseline (speedup 1.0000x reference)
#include <cuda_runtime.h>
#include <math.h>

// Problem constants
#define NB   2
#define HH   256
#define WW   256
#define CC   64
#define GG   4
#define PP   9
#define NPIX (NB*HH*WW)   // 131072

// Scratch (device bss — no allocation at runtime)
__device__ float g_y[NPIX*CC];        // conv+relu output, NHWC
__device__ float g_xproj[NPIX*CC];    // input projection, NHWC
__device__ float g_x1[NPIX*CC];       // dwconv+LN+GELU, NHWC
__device__ float g_off[NPIX*72];      // raw offsets (G*P*2)
__device__ float g_mask[NPIX*36];     // mask logits (softmax applied in k4 preload)
__device__ float g_wT[64*9*64];       // conv weight transposed: [ci][tap][oc]

// ---------------------------------------------------------------------------
// K0: transpose conv weights (oc,ci,kh,kw) -> (ci,tap,oc) for coalesced smem fill
// ---------------------------------------------------------------------------
__global__ void k0_transpose(const float* __restrict__ w) {
    int i = blockIdx.x * blockDim.x + threadIdx.x;
    if (i < 64*64*9) {
        int oc  = i / 576;
        int ci  = (i / 9) % 64;
        int tap = i % 9;
        g_wT[(ci*9 + tap)*64 + oc] = w[i];
    }
}

// ---------------------------------------------------------------------------
// K1: stride-2 3x3 conv (64->64) + ReLU, NCHW input -> NHWC output
// Block: 128 threads, tile = 1 out row x 64 cols x 64 oc.
// Thread tile: 8 oc x 4 px registers.
// ---------------------------------------------------------------------------
__global__ __launch_bounds__(128) void k1_conv(const float* __restrict__ x) {
    __shared__ float sp[3*132*9];   // patch [ky][col 0..128 (pad 132)][ci (pad 9)]
    __shared__ float sw[8*9*64];    // weights [ci][tap][oc]

    const int w0  = blockIdx.x * 64;
    const int h   = blockIdx.y;
    const int n   = blockIdx.z;
    const int tid = threadIdx.x;
    const int ocg = tid & 7;     // 8 groups of 8 oc
    const int pxg = tid >> 3;    // 16 groups of 4 px
    const int oc0 = ocg * 8;
    const int p0  = pxg * 4;

    float acc[4][8];
    #pragma unroll
    for (int a = 0; a < 4; ++a)
        #pragma unroll
        for (int b = 0; b < 8; ++b) acc[a][b] = 0.f;

    for (int ci0 = 0; ci0 < 64; ci0 += 8) {
        __syncthreads();
        // load input patch: 3 rows x 129 cols x 8 ci (zero padded)
        for (int idx = tid; idx < 8*3*129; idx += 128) {
            int ci = idx / (3*129);
            int r  = idx % (3*129);
            int ky = r / 129;
            int c  = r % 129;
            int row = 2*h - 1 + ky;
            int col = 2*w0 - 1 + c;
            float v = 0.f;
            if (row >= 0 && row < 512 && col >= 0 && col < 512)
                v = x[((size_t)(n*64 + ci0 + ci)*512 + row)*512 + col];
            sp[(ky*132 + c)*9 + ci] = v;
        }
        // load weight chunk (contiguous slice of g_wT)
        for (int idx = tid; idx < 8*9*64; idx += 128)
            sw[idx] = g_wT[ci0*9*64 + idx];
        __syncthreads();

        #pragma unroll
        for (int ci = 0; ci < 8; ++ci) {
            #pragma unroll
            for (int ky = 0; ky < 3; ++ky) {
                float in9[9];
                #pragma unroll
                for (int q = 0; q < 9; ++q)
                    in9[q] = sp[(ky*132 + 2*p0 + q)*9 + ci];
                #pragma unroll
                for (int kx = 0; kx < 3; ++kx) {
                    const float* wp = &sw[(ci*9 + ky*3 + kx)*64 + oc0];
                    float4 wa = *(const float4*)wp;
                    float4 wb = *(const float4*)(wp + 4);
                    #pragma unroll
                    for (int px = 0; px < 4; ++px) {
                        float v = in9[2*px + kx];
                        acc[px][0] += wa.x*v; acc[px][1] += wa.y*v;
                        acc[px][2] += wa.z*v; acc[px][3] += wa.w*v;
                        acc[px][4] += wb.x*v; acc[px][5] += wb.y*v;
                        acc[px][6] += wb.z*v; acc[px][7] += wb.w*v;
                    }
                }
            }
        }
    }

    const int pixbase = (n*256 + h)*256 + w0;
    #pragma unroll
    for (int px = 0; px < 4; ++px) {
        float* dst = &g_y[(size_t)(pixbase + p0 + px)*64 + oc0];
        float4 o1, o2;
        o1.x = fmaxf(acc[px][0], 0.f); o1.y = fmaxf(acc[px][1], 0.f);
        o1.z = fmaxf(acc[px][2], 0.f); o1.w = fmaxf(acc[px][3], 0.f);
        o2.x = fmaxf(acc[px][4], 0.f); o2.y = fmaxf(acc[px][5], 0.f);
        o2.z = fmaxf(acc[px][6], 0.f); o2.w = fmaxf(acc[px][7], 0.f);
        *(float4*)dst       = o1;
        *(float4*)(dst + 4) = o2;
    }
}

// ---------------------------------------------------------------------------
// K2: x_proj = y @ w_in + b_in   (64x64 GEMM per 64-pixel tile)
// ---------------------------------------------------------------------------
__global__ __launch_bounds__(256) void k2_xproj(const float* __restrict__ w_in,
                                                const float* __restrict__ b_in) {
    __shared__ float ys[64*65];
    __shared__ float ws[64*64];
    const int px0 = blockIdx.x * 64;
    const int tid = threadIdx.x;

    for (int idx = tid; idx < 4096; idx += 256) {
        int p = idx >> 6, k = idx & 63;
        ys[p*65 + k] = g_y[(size_t)px0*64 + idx];
        ws[idx]      = w_in[idx];
    }
    __syncthreads();

    const int ocg = tid & 15, pxg = tid >> 4;
    const int oc0 = ocg * 4, p0 = pxg * 4;
    float4 bv = *(const float4*)&b_in[oc0];
    float4 acc[4];
    #pragma unroll
    for (int i = 0; i < 4; ++i) acc[i] = bv;

    for (int k = 0; k < 64; ++k) {
        float4 wv = *(const float4*)&ws[k*64 + oc0];
        #pragma unroll
        for (int i = 0; i < 4; ++i) {
            float xv = ys[(p0 + i)*65 + k];
            acc[i].x += xv*wv.x; acc[i].y += xv*wv.y;
            acc[i].z += xv*wv.z; acc[i].w += xv*wv.w;
        }
    }
    #pragma unroll
    for (int i = 0; i < 4; ++i)
        *(float4*)&g_xproj[(size_t)(px0 + p0 + i)*64 + oc0] = acc[i];
}

// ---------------------------------------------------------------------------
// K3a: x1 = GELU(LayerNorm(dwconv3x3(y) + dw_b))    (one warp per pixel)
// ---------------------------------------------------------------------------
__global__ __launch_bounds__(256) void k3a_x1(const float* __restrict__ dw_w,
                                              const float* __restrict__ dw_b,
                                              const float* __restrict__ ln_g,
                                              const float* __restrict__ ln_b) {
    const int warp = threadIdx.x >> 5, lane = threadIdx.x & 31;
    const int px = blockIdx.x * 8 + warp;
    const int n = px >> 16, h = (px >> 8) & 255, w = px & 255;

    float v0 = dw_b[lane], v1 = dw_b[lane + 32];
    #pragma unroll
    for (int ky = 0; ky < 3; ++ky) {
        int hh = h + ky - 1;
        if (hh < 0 || hh >= 256) continue;
        #pragma unroll
        for (int kx = 0; kx < 3; ++kx) {
            int wc = w + kx - 1;
            if (wc < 0 || wc >= 256) continue;
            const float* yp = &g_y[(size_t)((n*256 + hh)*256 + wc)*64];
            int tap = ky*3 + kx;
            v0 += yp[lane]      * dw_w[tap*64 + lane];
            v1 += yp[lane + 32] * dw_w[tap*64 + lane + 32];
        }
    }
    float s  = v0 + v1;
    float sq = v0*v0 + v1*v1;
    #pragma unroll
    for (int o = 16; o > 0; o >>= 1) {
        s  += __shfl_xor_sync(0xFFFFFFFFu, s,  o);
        sq += __shfl_xor_sync(0xFFFFFFFFu, sq, o);
    }
    float m   = s * (1.f/64.f);
    float var = sq * (1.f/64.f) - m*m;
    float inv = rsqrtf(var + 1e-5f);

    {
        float t = (v0 - m)*inv*ln_g[lane] + ln_b[lane];
        g_x1[(size_t)px*64 + lane] = t * normcdff(t);
        float u = (v1 - m)*inv*ln_g[lane + 32] + ln_b[lane + 32];
        g_x1[(size_t)px*64 + lane + 32] = u * normcdff(u);
    }
}

// ---------------------------------------------------------------------------
// K3b: offset = x1 @ w_off + b_off ; mask_logits = x1 @ w_mask + b_mask
// Combined 64x112 GEMM (cols 0..71 offset, 72..107 mask, 108..111 pad).
// ---------------------------------------------------------------------------
__global__ __launch_bounds__(256) void k3b_offmask(const float* __restrict__ w_off,
                                                   const float* __restrict__ b_off,
                                                   const float* __restrict__ w_mask,
                                                   const float* __restrict__ b_mask) {
    __shared__ float xs[64*65];
    __shared__ float ws[64*112];
    const int px0 = blockIdx.x * 64;
    const int tid = threadIdx.x;

    for (int idx = tid; idx < 4096; idx += 256) {
        int p = idx >> 6, k = idx & 63;
        xs[p*65 + k] = g_x1[(size_t)px0*64 + idx];
    }
    for (int idx = tid; idx < 64*112; idx += 256) {
        int k = idx / 112, oc = idx % 112;
        float v = 0.f;
        if (oc < 72)       v = w_off[k*72 + oc];
        else if (oc < 108) v = w_mask[k*36 + oc - 72];
        ws[idx] = v;
    }
    __syncthreads();

    const int ocg = tid & 15, pxg = tid >> 4;
    const int p0 = pxg * 4;

    for (int half = 0; half < 2; ++half) {
        int oc0 = ocg*4 + half*64;
        if (oc0 >= 112) break;
        float acc[4][4];
        #pragma unroll
        for (int j = 0; j < 4; ++j) {
            int oc = oc0 + j;
            float b = (oc < 72) ? b_off[oc] : ((oc < 108) ? b_mask[oc - 72] : 0.f);
            #pragma unroll
            for (int i = 0; i < 4; ++i) acc[i][j] = b;
        }
        for (int k = 0; k < 64; ++k) {
            float4 wv = *(const float4*)&ws[k*112 + oc0];
            #pragma unroll
            for (int i = 0; i < 4; ++i) {
                float xv = xs[(p0 + i)*65 + k];
                acc[i][0] += xv*wv.x; acc[i][1] += xv*wv.y;
                acc[i][2] += xv*wv.z; acc[i][3] += xv*wv.w;
            }
        }
        #pragma unroll
        for (int i = 0; i < 4; ++i) {
            int px = px0 + p0 + i;
            #pragma unroll
            for (int j = 0; j < 4; ++j) {
                int oc = oc0 + j;
                if (oc < 72)       g_off[(size_t)px*72 + oc]        = acc[i][j];
                else if (oc < 108) g_mask[(size_t)px*36 + oc - 72]  = acc[i][j];
            }
        }
    }
}

// ---------------------------------------------------------------------------
// K4: DCNv3 bilinear gather (+softmax of mask logits) + output projection,
// writes final NCHW output. 16 pixels per block, 256 threads.
// Gather: thread = (pixel, group, 4-channel chunk) -> float4 accumulator.
// ---------------------------------------------------------------------------
__global__ __launch_bounds__(256) void k4_dcn(const float* __restrict__ w_out,
                                              const float* __restrict__ b_out,
                                              float* __restrict__ out) {
    __shared__ float ws[64*64];
    __shared__ float msh[16*36];
    __shared__ float osh[16*72];
    __shared__ float dsh[16*65];

    const int px0 = blockIdx.x * 16;
    const int tid = threadIdx.x;

    for (int idx = tid; idx < 4096; idx += 256) ws[idx] = w_out[idx];
    for (int idx = tid; idx < 16*36; idx += 256) msh[idx] = g_mask[(size_t)px0*36 + idx];
    for (int idx = tid; idx < 16*72; idx += 256) osh[idx] = g_off[(size_t)px0*72 + idx];
    __syncthreads();

    // softmax over P per (pixel, group)
    if (tid < 64) {
        int p = tid >> 2, g = tid & 3;
        float* mp = &msh[p*36 + g*9];
        float mx = mp[0];
        #pragma unroll
        for (int q = 1; q < 9; ++q) mx = fmaxf(mx, mp[q]);
        float ssum = 0.f;
        #pragma unroll
        for (int q = 0; q < 9; ++q) { float e = expf(mp[q] - mx); mp[q] = e; ssum += e; }
        float r = 1.f / ssum;
        #pragma unroll
        for (int q = 0; q < 9; ++q) mp[q] *= r;
    }
    __syncthreads();

    // ---- deformable gather ----
    {
        const int pxl = tid >> 4;        // 0..15
        const int sub = tid & 15;
        const int g = sub >> 2, c4 = sub & 3;
        const int px = px0 + pxl;
        const int n = px >> 16, h = (px >> 8) & 255, w = px & 255;

        float4 acc = make_float4(0.f, 0.f, 0.f, 0.f);
        const float* mrow = &msh[pxl*36 + g*9];
        const float* orow = &osh[pxl*72 + g*18];
        const float* xbase = g_xproj + (size_t)n*65536*64 + g*16 + c4*4;

        #pragma unroll
        for (int p = 0; p < 9; ++p) {
            float mwt = mrow[p];
            float ox = orow[p*2], oy = orow[p*2 + 1];
            // padded-grid coords: ix = w + 1 + (p/3 - 1) + ox ; iy = h + 1 + (p%3 - 1) + oy
            float ix = (float)(w + p/3) + ox;
            float iy = (float)(h + p%3) + oy;
            float x0f = floorf(ix), y0f = floorf(iy);
            float fx = ix - x0f, fy = iy - y0f;
            int x0 = (int)x0f, y0 = (int)y0f;
            float w00 = (1.f - fy)*(1.f - fx)*mwt;
            float w01 = (1.f - fy)*fx*mwt;
            float w10 = fy*(1.f - fx)*mwt;
            float w11 = fy*fx*mwt;

            #pragma unroll
            for (int corner = 0; corner < 4; ++corner) {
                int yc = y0 + (corner >> 1);
                int xc = x0 + (corner & 1);
                float wgt = (corner == 0) ? w00 : (corner == 1) ? w01
                          : (corner == 2) ? w10 : w11;
                if (xc >= 1 && xc <= 256 && yc >= 1 && yc <= 256) {
                    const float4 v = *(const float4*)(xbase + ((size_t)(yc-1)*256 + (xc-1))*64);
                    acc.x += wgt*v.x; acc.y += wgt*v.y;
                    acc.z += wgt*v.z; acc.w += wgt*v.w;
                }
            }
        }
        int cc = g*16 + c4*4;
        dsh[pxl*65 + cc + 0] = acc.x;
        dsh[pxl*65 + cc + 1] = acc.y;
        dsh[pxl*65 + cc + 2] = acc.z;
        dsh[pxl*65 + cc + 3] = acc.w;
    }
    __syncthreads();

    // ---- output projection + NCHW store ----
    {
        const int pxl = tid & 15;
        const int ocg = tid >> 4;
        const int oc0 = ocg * 4;
        float4 acc = *(const float4*)&b_out[oc0];
        for (int k = 0; k < 64; ++k) {
            float xv = dsh[pxl*65 + k];
            float4 wv = *(const float4*)&ws[k*64 + oc0];
            acc.x += xv*wv.x; acc.y += xv*wv.y;
            acc.z += xv*wv.z; acc.w += xv*wv.w;
        }
        const int px = px0 + pxl;
        const int n = px >> 16, h = (px >> 8) & 255, w = px & 255;
        size_t ob = ((size_t)(n*64 + oc0)*256 + h)*256 + w;
        out[ob]            = acc.x;
        out[ob + 65536]    = acc.y;
        out[ob + 2*65536]  = acc.z;
        out[ob + 3*65536]  = acc.w;
    }
}

// ---------------------------------------------------------------------------
extern "C" void kernel_launch(void* const* d_in, const int* in_sizes, int n_in,
                              void* d_out, int out_size) {
    const float* x      = (const float*)d_in[0];
    const float* conv_w = (const float*)d_in[1];
    const float* w_in   = (const float*)d_in[2];
    const float* b_in   = (const float*)d_in[3];
    const float* dw_w   = (const float*)d_in[4];
    const float* dw_b   = (const float*)d_in[5];
    const float* ln_g   = (const float*)d_in[6];
    const float* ln_b   = (const float*)d_in[7];
    const float* w_off  = (const float*)d_in[8];
    const float* b_off  = (const float*)d_in[9];
    const float* w_mask = (const float*)d_in[10];
    const float* b_mask = (const float*)d_in[11];
    const float* w_out  = (const float*)d_in[12];
    const float* b_out  = (const float*)d_in[13];
    float* out = (float*)d_out;

    k0_transpose<<<144, 256>>>(conv_w);
    dim3 g1(4, 256, 2);
    k1_conv<<<g1, 128>>>(x);
    k2_xproj<<<2048, 256>>>(w_in, b_in);
    k3a_x1<<<16384, 256>>>(dw_w, dw_b, ln_g, ln_b);
    k3b_offmask<<<2048, 256>>>(w_off, b_off, w_mask, b_mask);
    k4_dcn<<<8192, 256>>>(w_out, b_out, out);
}

// round 7
// speedup vs baseline: 1.2942x; 1.2942x over previous
#include <cuda_runtime.h>
#include <math.h>

// Problem constants
#define NB   2
#define HH   256
#define WW   256
#define CC   64
#define GG   4
#define PP   9
#define NPIX (NB*HH*WW)   // 131072

typedef unsigned long long u64;

// packed f32x2 helpers (sm_100+ PTX; doubles fp32 FMA throughput vs scalar FFMA)
__device__ __forceinline__ u64 pk2(float v) {
    u64 r; asm("mov.b64 %0, {%1, %1};" : "=l"(r) : "f"(v)); return r;
}
__device__ __forceinline__ u64 pk(float lo, float hi) {
    u64 r; asm("mov.b64 %0, {%1, %2};" : "=l"(r) : "f"(lo), "f"(hi)); return r;
}
__device__ __forceinline__ void upk(u64 v, float& lo, float& hi) {
    asm("mov.b64 {%0, %1}, %2;" : "=f"(lo), "=f"(hi) : "l"(v));
}
__device__ __forceinline__ void fma2(u64& d, u64 a, u64 b) {
    asm("fma.rn.f32x2 %0, %1, %2, %3;" : "=l"(d) : "l"(a), "l"(b), "l"(d));
}

// Scratch (device bss — no allocation at runtime)
__device__ float g_y[NPIX*CC];        // conv+relu output, NHWC
__device__ float g_xproj[NPIX*CC];    // input projection, NHWC
__device__ float g_x1[NPIX*CC];       // dwconv+LN+GELU, NHWC
__device__ float g_off[NPIX*72];      // raw offsets (G*P*2)
__device__ float g_mask[NPIX*36];     // mask logits (softmax applied in k4 preload)
__device__ float g_wT[64*9*64];       // conv weight transposed: [ci][tap][oc]

// ---------------------------------------------------------------------------
// K0: transpose conv weights (oc,ci,kh,kw) -> (ci,tap,oc)
// ---------------------------------------------------------------------------
__global__ void k0_transpose(const float* __restrict__ w) {
    int i = blockIdx.x * blockDim.x + threadIdx.x;
    if (i < 64*64*9) {
        int oc  = i / 576;
        int ci  = (i / 9) % 64;
        int tap = i % 9;
        g_wT[(ci*9 + tap)*64 + oc] = w[i];
    }
}

// ---------------------------------------------------------------------------
// K1: stride-2 3x3 conv (64->64) + ReLU, NCHW input -> NHWC output
// f32x2 packed accumulators: thread tile = 4 px x 4 oc-pairs (8 oc).
// Patch smem layout [ci][ky][col] -> the 9 taps per (ci,ky) are contiguous,
// loaded as 2x LDS.128 + 1x LDS.32 (was 9 scalar LDS).
// ---------------------------------------------------------------------------
__global__ __launch_bounds__(128) void k1_conv(const float* __restrict__ x) {
    __shared__ float sp[8*3*132];   // patch [ci][ky][col 0..128 (pad 132)]
    __shared__ float sw[8*9*64];    // weights [ci][tap][oc]

    const int w0  = blockIdx.x * 64;
    const int h   = blockIdx.y;
    const int n   = blockIdx.z;
    const int tid = threadIdx.x;
    const int ocg = tid & 7;     // 8 groups of 8 oc
    const int pxg = tid >> 3;    // 16 groups of 4 px
    const int oc0 = ocg * 8;
    const int p0  = pxg * 4;

    u64 acc[4][4];
    #pragma unroll
    for (int a = 0; a < 4; ++a)
        #pragma unroll
        for (int b = 0; b < 4; ++b) acc[a][b] = 0ull;

    for (int ci0 = 0; ci0 < 64; ci0 += 8) {
        __syncthreads();
        // load input patch: 8 ci x 3 rows x 129 cols (zero padded)
        for (int idx = tid; idx < 8*3*129; idx += 128) {
            int ci = idx / (3*129);
            int r  = idx % (3*129);
            int ky = r / 129;
            int c  = r % 129;
            int row = 2*h - 1 + ky;
            int col = 2*w0 - 1 + c;
            float v = 0.f;
            if (row >= 0 && row < 512 && col >= 0 && col < 512)
                v = x[((size_t)(n*64 + ci0 + ci)*512 + row)*512 + col];
            sp[(ci*3 + ky)*132 + c] = v;
        }
        // load weight chunk (contiguous slice of g_wT)
        for (int idx = tid; idx < 8*9*64; idx += 128)
            sw[idx] = g_wT[ci0*9*64 + idx];
        __syncthreads();

        #pragma unroll
        for (int ci = 0; ci < 8; ++ci) {
            #pragma unroll
            for (int ky = 0; ky < 3; ++ky) {
                const float* rp = &sp[(ci*3 + ky)*132 + 2*p0];  // 32B aligned
                float4 ra = *(const float4*)rp;
                float4 rb = *(const float4*)(rp + 4);
                float  rc = rp[8];
                u64 in2[9];
                in2[0] = pk2(ra.x); in2[1] = pk2(ra.y); in2[2] = pk2(ra.z);
                in2[3] = pk2(ra.w); in2[4] = pk2(rb.x); in2[5] = pk2(rb.y);
                in2[6] = pk2(rb.z); in2[7] = pk2(rb.w); in2[8] = pk2(rc);
                #pragma unroll
                for (int kx = 0; kx < 3; ++kx) {
                    const u64* wp = (const u64*)&sw[(ci*9 + ky*3 + kx)*64 + oc0];
                    u64 wv0 = wp[0], wv1 = wp[1], wv2 = wp[2], wv3 = wp[3];
                    #pragma unroll
                    for (int px = 0; px < 4; ++px) {
                        u64 v = in2[2*px + kx];
                        fma2(acc[px][0], wv0, v);
                        fma2(acc[px][1], wv1, v);
                        fma2(acc[px][2], wv2, v);
                        fma2(acc[px][3], wv3, v);
                    }
                }
            }
        }
    }

    const int pixbase = (n*256 + h)*256 + w0;
    #pragma unroll
    for (int px = 0; px < 4; ++px) {
        float* dst = &g_y[(size_t)(pixbase + p0 + px)*64 + oc0];
        float4 o1, o2;
        float a, b;
        upk(acc[px][0], a, b); o1.x = fmaxf(a, 0.f); o1.y = fmaxf(b, 0.f);
        upk(acc[px][1], a, b); o1.z = fmaxf(a, 0.f); o1.w = fmaxf(b, 0.f);
        upk(acc[px][2], a, b); o2.x = fmaxf(a, 0.f); o2.y = fmaxf(b, 0.f);
        upk(acc[px][3], a, b); o2.z = fmaxf(a, 0.f); o2.w = fmaxf(b, 0.f);
        *(float4*)dst       = o1;
        *(float4*)(dst + 4) = o2;
    }
}

// ---------------------------------------------------------------------------
// K2: x_proj = y @ w_in + b_in   (64x64 GEMM per 64-pixel tile), f32x2 packed
// ---------------------------------------------------------------------------
__global__ __launch_bounds__(256) void k2_xproj(const float* __restrict__ w_in,
                                                const float* __restrict__ b_in) {
    __shared__ float ys[64*65];
    __shared__ float ws[64*64];
    const int px0 = blockIdx.x * 64;
    const int tid = threadIdx.x;

    for (int idx = tid; idx < 4096; idx += 256) {
        int p = idx >> 6, k = idx & 63;
        ys[p*65 + k] = g_y[(size_t)px0*64 + idx];
        ws[idx]      = w_in[idx];
    }
    __syncthreads();

    const int ocg = tid & 15, pxg = tid >> 4;
    const int oc0 = ocg * 4, p0 = pxg * 4;
    float4 bv = *(const float4*)&b_in[oc0];
    u64 acc[4][2];
    #pragma unroll
    for (int i = 0; i < 4; ++i) { acc[i][0] = pk(bv.x, bv.y); acc[i][1] = pk(bv.z, bv.w); }

    for (int k = 0; k < 64; ++k) {
        const u64* wp = (const u64*)&ws[k*64 + oc0];
        u64 w0 = wp[0], w1 = wp[1];
        #pragma unroll
        for (int i = 0; i < 4; ++i) {
            u64 xv = pk2(ys[(p0 + i)*65 + k]);
            fma2(acc[i][0], w0, xv);
            fma2(acc[i][1], w1, xv);
        }
    }
    #pragma unroll
    for (int i = 0; i < 4; ++i) {
        ulonglong2 o; o.x = acc[i][0]; o.y = acc[i][1];
        *(ulonglong2*)&g_xproj[(size_t)(px0 + p0 + i)*64 + oc0] = o;
    }
}

// ---------------------------------------------------------------------------
// K3a: x1 = GELU(LayerNorm(dwconv3x3(y) + dw_b))    (one warp per pixel)
// ---------------------------------------------------------------------------
__global__ __launch_bounds__(256) void k3a_x1(const float* __restrict__ dw_w,
                                              const float* __restrict__ dw_b,
                                              const float* __restrict__ ln_g,
                                              const float* __restrict__ ln_b) {
    const int warp = threadIdx.x >> 5, lane = threadIdx.x & 31;
    const int px = blockIdx.x * 8 + warp;
    const int n = px >> 16, h = (px >> 8) & 255, w = px & 255;

    float v0 = dw_b[lane], v1 = dw_b[lane + 32];
    #pragma unroll
    for (int ky = 0; ky < 3; ++ky) {
        int hh = h + ky - 1;
        if (hh < 0 || hh >= 256) continue;
        #pragma unroll
        for (int kx = 0; kx < 3; ++kx) {
            int wc = w + kx - 1;
            if (wc < 0 || wc >= 256) continue;
            const float* yp = &g_y[(size_t)((n*256 + hh)*256 + wc)*64];
            int tap = ky*3 + kx;
            v0 += yp[lane]      * dw_w[tap*64 + lane];
            v1 += yp[lane + 32] * dw_w[tap*64 + lane + 32];
        }
    }
    float s  = v0 + v1;
    float sq = v0*v0 + v1*v1;
    #pragma unroll
    for (int o = 16; o > 0; o >>= 1) {
        s  += __shfl_xor_sync(0xFFFFFFFFu, s,  o);
        sq += __shfl_xor_sync(0xFFFFFFFFu, sq, o);
    }
    float m   = s * (1.f/64.f);
    float var = sq * (1.f/64.f) - m*m;
    float inv = rsqrtf(var + 1e-5f);

    {
        float t = (v0 - m)*inv*ln_g[lane] + ln_b[lane];
        g_x1[(size_t)px*64 + lane] = t * normcdff(t);
        float u = (v1 - m)*inv*ln_g[lane + 32] + ln_b[lane + 32];
        g_x1[(size_t)px*64 + lane + 32] = u * normcdff(u);
    }
}

// ---------------------------------------------------------------------------
// K3b: offset = x1 @ w_off + b_off ; mask_logits = x1 @ w_mask + b_mask
// Combined 64x112 GEMM, f32x2 packed.
// ---------------------------------------------------------------------------
__global__ __launch_bounds__(256) void k3b_offmask(const float* __restrict__ w_off,
                                                   const float* __restrict__ b_off,
                                                   const float* __restrict__ w_mask,
                                                   const float* __restrict__ b_mask) {
    __shared__ float xs[64*65];
    __shared__ float ws[64*112];
    const int px0 = blockIdx.x * 64;
    const int tid = threadIdx.x;

    for (int idx = tid; idx < 4096; idx += 256) {
        int p = idx >> 6, k = idx & 63;
        xs[p*65 + k] = g_x1[(size_t)px0*64 + idx];
    }
    for (int idx = tid; idx < 64*112; idx += 256) {
        int k = idx / 112, oc = idx % 112;
        float v = 0.f;
        if (oc < 72)       v = w_off[k*72 + oc];
        else if (oc < 108) v = w_mask[k*36 + oc - 72];
        ws[idx] = v;
    }
    __syncthreads();

    const int ocg = tid & 15, pxg = tid >> 4;
    const int p0 = pxg * 4;

    for (int half = 0; half < 2; ++half) {
        int oc0 = ocg*4 + half*64;
        if (oc0 >= 112) break;
        u64 acc[4][2];
        {
            float bb[4];
            #pragma unroll
            for (int j = 0; j < 4; ++j) {
                int oc = oc0 + j;
                bb[j] = (oc < 72) ? b_off[oc] : ((oc < 108) ? b_mask[oc - 72] : 0.f);
            }
            #pragma unroll
            for (int i = 0; i < 4; ++i) { acc[i][0] = pk(bb[0], bb[1]); acc[i][1] = pk(bb[2], bb[3]); }
        }
        for (int k = 0; k < 64; ++k) {
            const u64* wp = (const u64*)&ws[k*112 + oc0];
            u64 w0 = wp[0], w1 = wp[1];
            #pragma unroll
            for (int i = 0; i < 4; ++i) {
                u64 xv = pk2(xs[(p0 + i)*65 + k]);
                fma2(acc[i][0], w0, xv);
                fma2(acc[i][1], w1, xv);
            }
        }
        #pragma unroll
        for (int i = 0; i < 4; ++i) {
            int px = px0 + p0 + i;
            float v01[2], v23[2];
            upk(acc[i][0], v01[0], v01[1]);
            upk(acc[i][1], v23[0], v23[1]);
            #pragma unroll
            for (int j = 0; j < 4; ++j) {
                int oc = oc0 + j;
                float v = (j < 2) ? v01[j] : v23[j - 2];
                if (oc < 72)       g_off[(size_t)px*72 + oc]       = v;
                else if (oc < 108) g_mask[(size_t)px*36 + oc - 72] = v;
            }
        }
    }
}

// ---------------------------------------------------------------------------
// K4: DCNv3 bilinear gather (+softmax) + output projection -> NCHW output.
// 16 pixels per block, 256 threads. Projection loop uses f32x2.
// ---------------------------------------------------------------------------
__global__ __launch_bounds__(256) void k4_dcn(const float* __restrict__ w_out,
                                              const float* __restrict__ b_out,
                                              float* __restrict__ out) {
    __shared__ float ws[64*64];
    __shared__ float msh[16*36];
    __shared__ float osh[16*72];
    __shared__ float dsh[16*65];

    const int px0 = blockIdx.x * 16;
    const int tid = threadIdx.x;

    for (int idx = tid; idx < 4096; idx += 256) ws[idx] = w_out[idx];
    for (int idx = tid; idx < 16*36; idx += 256) msh[idx] = g_mask[(size_t)px0*36 + idx];
    for (int idx = tid; idx < 16*72; idx += 256) osh[idx] = g_off[(size_t)px0*72 + idx];
    __syncthreads();

    // softmax over P per (pixel, group)
    if (tid < 64) {
        int p = tid >> 2, g = tid & 3;
        float* mp = &msh[p*36 + g*9];
        float mx = mp[0];
        #pragma unroll
        for (int q = 1; q < 9; ++q) mx = fmaxf(mx, mp[q]);
        float ssum = 0.f;
        #pragma unroll
        for (int q = 0; q < 9; ++q) { float e = expf(mp[q] - mx); mp[q] = e; ssum += e; }
        float r = 1.f / ssum;
        #pragma unroll
        for (int q = 0; q < 9; ++q) mp[q] *= r;
    }
    __syncthreads();

    // ---- deformable gather ----
    {
        const int pxl = tid >> 4;        // 0..15
        const int sub = tid & 15;
        const int g = sub >> 2, c4 = sub & 3;
        const int px = px0 + pxl;
        const int n = px >> 16, h = (px >> 8) & 255, w = px & 255;

        float4 acc = make_float4(0.f, 0.f, 0.f, 0.f);
        const float* mrow = &msh[pxl*36 + g*9];
        const float* orow = &osh[pxl*72 + g*18];
        const float* xbase = g_xproj + (size_t)n*65536*64 + g*16 + c4*4;

        #pragma unroll
        for (int p = 0; p < 9; ++p) {
            float mwt = mrow[p];
            float ox = orow[p*2], oy = orow[p*2 + 1];
            float ix = (float)(w + p/3) + ox;
            float iy = (float)(h + p%3) + oy;
            float x0f = floorf(ix), y0f = floorf(iy);
            float fx = ix - x0f, fy = iy - y0f;
            int x0 = (int)x0f, y0 = (int)y0f;
            float w00 = (1.f - fy)*(1.f - fx)*mwt;
            float w01 = (1.f - fy)*fx*mwt;
            float w10 = fy*(1.f - fx)*mwt;
            float w11 = fy*fx*mwt;

            #pragma unroll
            for (int corner = 0; corner < 4; ++corner) {
                int yc = y0 + (corner >> 1);
                int xc = x0 + (corner & 1);
                float wgt = (corner == 0) ? w00 : (corner == 1) ? w01
                          : (corner == 2) ? w10 : w11;
                if (xc >= 1 && xc <= 256 && yc >= 1 && yc <= 256) {
                    const float4 v = *(const float4*)(xbase + ((size_t)(yc-1)*256 + (xc-1))*64);
                    acc.x += wgt*v.x; acc.y += wgt*v.y;
                    acc.z += wgt*v.z; acc.w += wgt*v.w;
                }
            }
        }
        int cc = g*16 + c4*4;
        dsh[pxl*65 + cc + 0] = acc.x;
        dsh[pxl*65 + cc + 1] = acc.y;
        dsh[pxl*65 + cc + 2] = acc.z;
        dsh[pxl*65 + cc + 3] = acc.w;
    }
    __syncthreads();

    // ---- output projection (f32x2) + NCHW store ----
    {
        const int pxl = tid & 15;
        const int ocg = tid >> 4;
        const int oc0 = ocg * 4;
        float4 bv = *(const float4*)&b_out[oc0];
        u64 a0 = pk(bv.x, bv.y), a1 = pk(bv.z, bv.w);
        for (int k = 0; k < 64; ++k) {
            u64 xv = pk2(dsh[pxl*65 + k]);
            const u64* wp = (const u64*)&ws[k*64 + oc0];
            fma2(a0, wp[0], xv);
            fma2(a1, wp[1], xv);
        }
        const int px = px0 + pxl;
        const int n = px >> 16, h = (px >> 8) & 255, w = px & 255;
        size_t ob = ((size_t)(n*64 + oc0)*256 + h)*256 + w;
        float r0, r1, r2, r3;
        upk(a0, r0, r1); upk(a1, r2, r3);
        out[ob]            = r0;
        out[ob + 65536]    = r1;
        out[ob + 2*65536]  = r2;
        out[ob + 3*65536]  = r3;
    }
}

// ---------------------------------------------------------------------------
extern "C" void kernel_launch(void* const* d_in, const int* in_sizes, int n_in,
                              void* d_out, int out_size) {
    const float* x      = (const float*)d_in[0];
    const float* conv_w = (const float*)d_in[1];
    const float* w_in   = (const float*)d_in[2];
    const float* b_in   = (const float*)d_in[3];
    const float* dw_w   = (const float*)d_in[4];
    const float* dw_b   = (const float*)d_in[5];
    const float* ln_g   = (const float*)d_in[6];
    const float* ln_b   = (const float*)d_in[7];
    const float* w_off  = (const float*)d_in[8];
    const float* b_off  = (const float*)d_in[9];
    const float* w_mask = (const float*)d_in[10];
    const float* b_mask = (const float*)d_in[11];
    const float* w_out  = (const float*)d_in[12];
    const float* b_out  = (const float*)d_in[13];
    float* out = (float*)d_out;

    k0_transpose<<<144, 256>>>(conv_w);
    dim3 g1(4, 256, 2);
    k1_conv<<<g1, 128>>>(x);
    k2_xproj<<<2048, 256>>>(w_in, b_in);
    k3a_x1<<<16384, 256>>>(dw_w, dw_b, ln_g, ln_b);
    k3b_offmask<<<2048, 256>>>(w_off, b_off, w_mask, b_mask);
    k4_dcn<<<8192, 256>>>(w_out, b_out, out);
}

// round 10
// speedup vs baseline: 1.4156x; 1.0938x over previous
#include <cuda_runtime.h>
#include <cuda_fp16.h>
#include <math.h>

// Problem constants
#define NB   2
#define HH   256
#define WW   256
#define CC   64
#define GG   4
#define PP   9
#define NPIX (NB*HH*WW)   // 131072

typedef unsigned long long u64;

// packed f32x2 helpers (sm_100+ PTX; doubles fp32 FMA throughput vs scalar FFMA)
__device__ __forceinline__ u64 pk2(float v) {
    u64 r; asm("mov.b64 %0, {%1, %1};" : "=l"(r) : "f"(v)); return r;
}
__device__ __forceinline__ u64 pk(float lo, float hi) {
    u64 r; asm("mov.b64 %0, {%1, %2};" : "=l"(r) : "f"(lo), "f"(hi)); return r;
}
__device__ __forceinline__ void upk(u64 v, float& lo, float& hi) {
    asm("mov.b64 {%0, %1}, %2;" : "=f"(lo), "=f"(hi) : "l"(v));
}
__device__ __forceinline__ void fma2(u64& d, u64 a, u64 b) {
    asm("fma.rn.f32x2 %0, %1, %2, %3;" : "=l"(d) : "l"(a), "l"(b), "l"(d));
}

// cp.async helpers
__device__ __forceinline__ unsigned smem_u32(const void* p) {
    return (unsigned)__cvta_generic_to_shared(p);
}
__device__ __forceinline__ void cp4(unsigned dst, const float* src, bool ok) {
    int sz = ok ? 4 : 0;
    asm volatile("cp.async.ca.shared.global [%0], [%1], 4, %2;\n"
                 :: "r"(dst), "l"(src), "r"(sz));
}
__device__ __forceinline__ void cp16(unsigned dst, const void* src) {
    asm volatile("cp.async.cg.shared.global [%0], [%1], 16;\n"
                 :: "r"(dst), "l"(src));
}
#define CP_COMMIT asm volatile("cp.async.commit_group;\n" ::: "memory")
#define CP_WAIT1  asm volatile("cp.async.wait_group 1;\n" ::: "memory")

// Scratch (device bss — no allocation at runtime)
__device__ float  g_y[NPIX*CC];        // conv+relu output, NHWC
__device__ __half g_xproj_h[NPIX*CC];  // input projection, NHWC, fp16 storage
__device__ float  g_x1[NPIX*CC];       // dwconv+LN+GELU, NHWC
__device__ float  g_off[NPIX*72];      // raw offsets (G*P*2)
__device__ float  g_mask[NPIX*36];     // mask logits (softmax applied in k4)
__device__ float  g_wT[64*9*64];       // conv weight transposed: [ci][tap][oc]

// ---------------------------------------------------------------------------
// K0: transpose conv weights (oc,ci,kh,kw) -> (ci,tap,oc)
// ---------------------------------------------------------------------------
__global__ void k0_transpose(const float* __restrict__ w) {
    int i = blockIdx.x * blockDim.x + threadIdx.x;
    if (i < 64*64*9) {
        int oc  = i / 576;
        int ci  = (i / 9) % 64;
        int tap = i % 9;
        g_wT[(ci*9 + tap)*64 + oc] = w[i];
    }
}

// ---------------------------------------------------------------------------
// K1: stride-2 3x3 conv (64->64) + ReLU, NCHW input -> NHWC output
// f32x2 accumulators; cp.async double-buffered pipeline over 16 chunks of 4 ci.
// ---------------------------------------------------------------------------
#define K1_CHUNKS 16
__global__ __launch_bounds__(128) void k1_conv(const float* __restrict__ x) {
    __shared__ float sp[2][1584];   // patch [ci 0..3][ky][col 0..128 (pad 132)]
    __shared__ float sw[2][2304];   // weights [ci 0..3][tap][oc]

    const int w0  = blockIdx.x * 64;
    const int h   = blockIdx.y;
    const int n   = blockIdx.z;
    const int tid = threadIdx.x;
    const int ocg = tid & 7;     // 8 groups of 8 oc
    const int pxg = tid >> 3;    // 16 groups of 4 px
    const int oc0 = ocg * 8;
    const int p0  = pxg * 4;

    u64 acc[4][4];
    #pragma unroll
    for (int a = 0; a < 4; ++a)
        #pragma unroll
        for (int b = 0; b < 4; ++b) acc[a][b] = 0ull;

    auto prefetch = [&](int chunk, int buf) {
        const int ci0 = chunk * 4;
        unsigned spb = smem_u32(&sp[buf][0]);
        unsigned swb = smem_u32(&sw[buf][0]);
        // patch: 4 ci x 3 rows x 129 cols, zero-filled at borders
        for (int idx = tid; idx < 4*3*129; idx += 128) {
            int ci = idx / 387;         // 3*129
            int r  = idx % 387;
            int ky = r / 129;
            int c  = r % 129;
            int row = 2*h - 1 + ky;
            int col = 2*w0 - 1 + c;
            bool ok = ((unsigned)row < 512u) && ((unsigned)col < 512u);
            const float* src = x + (ok ? ((size_t)(n*64 + ci0 + ci)*512 + row)*512 + col : 0);
            cp4(spb + (unsigned)(((ci*3 + ky)*132 + c)*4), src, ok);
        }
        // weights: contiguous 2304-float slice of g_wT, 16B vectors
        const float* wsrc = g_wT + (size_t)chunk*2304;
        for (int idx = tid; idx < 576; idx += 128)
            cp16(swb + (unsigned)(idx*16), wsrc + idx*4);
    };

    auto compute = [&](int buf) {
        #pragma unroll
        for (int ci = 0; ci < 4; ++ci) {
            #pragma unroll
            for (int ky = 0; ky < 3; ++ky) {
                const float* rp = &sp[buf][(ci*3 + ky)*132 + 2*p0];  // 32B aligned
                float4 ra = *(const float4*)rp;
                float4 rb = *(const float4*)(rp + 4);
                float  rc = rp[8];
                u64 in2[9];
                in2[0] = pk2(ra.x); in2[1] = pk2(ra.y); in2[2] = pk2(ra.z);
                in2[3] = pk2(ra.w); in2[4] = pk2(rb.x); in2[5] = pk2(rb.y);
                in2[6] = pk2(rb.z); in2[7] = pk2(rb.w); in2[8] = pk2(rc);
                #pragma unroll
                for (int kx = 0; kx < 3; ++kx) {
                    const u64* wp = (const u64*)&sw[buf][(ci*9 + ky*3 + kx)*64 + oc0];
                    u64 wv0 = wp[0], wv1 = wp[1], wv2 = wp[2], wv3 = wp[3];
                    #pragma unroll
                    for (int px = 0; px < 4; ++px) {
                        u64 v = in2[2*px + kx];
                        fma2(acc[px][0], wv0, v);
                        fma2(acc[px][1], wv1, v);
                        fma2(acc[px][2], wv2, v);
                        fma2(acc[px][3], wv3, v);
                    }
                }
            }
        }
    };

    prefetch(0, 0); CP_COMMIT;
    prefetch(1, 1); CP_COMMIT;
    for (int c = 0; c < K1_CHUNKS; ++c) {
        CP_WAIT1;                 // chunk c's group complete
        __syncthreads();
        compute(c & 1);
        __syncthreads();          // all readers done before buffer refill
        if (c + 2 < K1_CHUNKS) prefetch(c + 2, c & 1);
        CP_COMMIT;                // empty group near the tail keeps counts aligned
    }

    const int pixbase = (n*256 + h)*256 + w0;
    #pragma unroll
    for (int px = 0; px < 4; ++px) {
        float* dst = &g_y[(size_t)(pixbase + p0 + px)*64 + oc0];
        float4 o1, o2;
        float a, b;
        upk(acc[px][0], a, b); o1.x = fmaxf(a, 0.f); o1.y = fmaxf(b, 0.f);
        upk(acc[px][1], a, b); o1.z = fmaxf(a, 0.f); o1.w = fmaxf(b, 0.f);
        upk(acc[px][2], a, b); o2.x = fmaxf(a, 0.f); o2.y = fmaxf(b, 0.f);
        upk(acc[px][3], a, b); o2.z = fmaxf(a, 0.f); o2.w = fmaxf(b, 0.f);
        *(float4*)dst       = o1;
        *(float4*)(dst + 4) = o2;
    }
}

// ---------------------------------------------------------------------------
// K2: x_proj = y @ w_in + b_in  (64x64 GEMM per 64-pixel tile), f32x2 packed,
// fp16 output for the gather stage.
// ---------------------------------------------------------------------------
__global__ __launch_bounds__(256) void k2_xproj(const float* __restrict__ w_in,
                                                const float* __restrict__ b_in) {
    __shared__ float ys[64*65];
    __shared__ float ws[64*64];
    const int px0 = blockIdx.x * 64;
    const int tid = threadIdx.x;

    for (int idx = tid; idx < 4096; idx += 256) {
        int p = idx >> 6, k = idx & 63;
        ys[p*65 + k] = g_y[(size_t)px0*64 + idx];
        ws[idx]      = w_in[idx];
    }
    __syncthreads();

    const int ocg = tid & 15, pxg = tid >> 4;
    const int oc0 = ocg * 4, p0 = pxg * 4;
    float4 bv = *(const float4*)&b_in[oc0];
    u64 acc[4][2];
    #pragma unroll
    for (int i = 0; i < 4; ++i) { acc[i][0] = pk(bv.x, bv.y); acc[i][1] = pk(bv.z, bv.w); }

    for (int k = 0; k < 64; ++k) {
        const u64* wp = (const u64*)&ws[k*64 + oc0];
        u64 w0 = wp[0], w1 = wp[1];
        #pragma unroll
        for (int i = 0; i < 4; ++i) {
            u64 xv = pk2(ys[(p0 + i)*65 + k]);
            fma2(acc[i][0], w0, xv);
            fma2(acc[i][1], w1, xv);
        }
    }
    #pragma unroll
    for (int i = 0; i < 4; ++i) {
        float a, b, c, d;
        upk(acc[i][0], a, b); upk(acc[i][1], c, d);
        __half2 h0 = __floats2half2_rn(a, b);
        __half2 h1 = __floats2half2_rn(c, d);
        uint2 o;
        o.x = *(unsigned*)&h0; o.y = *(unsigned*)&h1;
        *(uint2*)&g_xproj_h[(size_t)(px0 + p0 + i)*64 + oc0] = o;
    }
}

// ---------------------------------------------------------------------------
// K3a: x1 = GELU(LayerNorm(dwconv3x3(y) + dw_b))    (one warp per pixel)
// ---------------------------------------------------------------------------
__global__ __launch_bounds__(256) void k3a_x1(const float* __restrict__ dw_w,
                                              const float* __restrict__ dw_b,
                                              const float* __restrict__ ln_g,
                                              const float* __restrict__ ln_b) {
    const int warp = threadIdx.x >> 5, lane = threadIdx.x & 31;
    const int px = blockIdx.x * 8 + warp;
    const int n = px >> 16, h = (px >> 8) & 255, w = px & 255;

    float v0 = dw_b[lane], v1 = dw_b[lane + 32];
    #pragma unroll
    for (int ky = 0; ky < 3; ++ky) {
        int hh = h + ky - 1;
        if (hh < 0 || hh >= 256) continue;
        #pragma unroll
        for (int kx = 0; kx < 3; ++kx) {
            int wc = w + kx - 1;
            if (wc < 0 || wc >= 256) continue;
            const float* yp = &g_y[(size_t)((n*256 + hh)*256 + wc)*64];
            int tap = ky*3 + kx;
            v0 += yp[lane]      * dw_w[tap*64 + lane];
            v1 += yp[lane + 32] * dw_w[tap*64 + lane + 32];
        }
    }
    float s  = v0 + v1;
    float sq = v0*v0 + v1*v1;
    #pragma unroll
    for (int o = 16; o > 0; o >>= 1) {
        s  += __shfl_xor_sync(0xFFFFFFFFu, s,  o);
        sq += __shfl_xor_sync(0xFFFFFFFFu, sq, o);
    }
    float m   = s * (1.f/64.f);
    float var = sq * (1.f/64.f) - m*m;
    float inv = rsqrtf(var + 1e-5f);

    {
        float t = (v0 - m)*inv*ln_g[lane] + ln_b[lane];
        g_x1[(size_t)px*64 + lane] = t * normcdff(t);
        float u = (v1 - m)*inv*ln_g[lane + 32] + ln_b[lane + 32];
        g_x1[(size_t)px*64 + lane + 32] = u * normcdff(u);
    }
}

// ---------------------------------------------------------------------------
// K3b: offset = x1 @ w_off + b_off ; mask_logits = x1 @ w_mask + b_mask
// Combined 64x112 GEMM, f32x2 packed.
// ---------------------------------------------------------------------------
__global__ __launch_bounds__(256) void k3b_offmask(const float* __restrict__ w_off,
                                                   const float* __restrict__ b_off,
                                                   const float* __restrict__ w_mask,
                                                   const float* __restrict__ b_mask) {
    __shared__ float xs[64*65];
    __shared__ float ws[64*112];
    const int px0 = blockIdx.x * 64;
    const int tid = threadIdx.x;

    for (int idx = tid; idx < 4096; idx += 256) {
        int p = idx >> 6, k = idx & 63;
        xs[p*65 + k] = g_x1[(size_t)px0*64 + idx];
    }
    for (int idx = tid; idx < 64*112; idx += 256) {
        int k = idx / 112, oc = idx % 112;
        float v = 0.f;
        if (oc < 72)       v = w_off[k*72 + oc];
        else if (oc < 108) v = w_mask[k*36 + oc - 72];
        ws[idx] = v;
    }
    __syncthreads();

    const int ocg = tid & 15, pxg = tid >> 4;
    const int p0 = pxg * 4;

    for (int half = 0; half < 2; ++half) {
        int oc0 = ocg*4 + half*64;
        if (oc0 >= 112) break;
        u64 acc[4][2];
        {
            float bb[4];
            #pragma unroll
            for (int j = 0; j < 4; ++j) {
                int oc = oc0 + j;
                bb[j] = (oc < 72) ? b_off[oc] : ((oc < 108) ? b_mask[oc - 72] : 0.f);
            }
            #pragma unroll
            for (int i = 0; i < 4; ++i) { acc[i][0] = pk(bb[0], bb[1]); acc[i][1] = pk(bb[2], bb[3]); }
        }
        for (int k = 0; k < 64; ++k) {
            const u64* wp = (const u64*)&ws[k*112 + oc0];
            u64 w0 = wp[0], w1 = wp[1];
            #pragma unroll
            for (int i = 0; i < 4; ++i) {
                u64 xv = pk2(xs[(p0 + i)*65 + k]);
                fma2(acc[i][0], w0, xv);
                fma2(acc[i][1], w1, xv);
            }
        }
        #pragma unroll
        for (int i = 0; i < 4; ++i) {
            int px = px0 + p0 + i;
            float v01[2], v23[2];
            upk(acc[i][0], v01[0], v01[1]);
            upk(acc[i][1], v23[0], v23[1]);
            #pragma unroll
            for (int j = 0; j < 4; ++j) {
                int oc = oc0 + j;
                float v = (j < 2) ? v01[j] : v23[j - 2];
                if (oc < 72)       g_off[(size_t)px*72 + oc]       = v;
                else if (oc < 108) g_mask[(size_t)px*36 + oc - 72] = v;
            }
        }
    }
}

// ---------------------------------------------------------------------------
// K4: DCNv3 bilinear gather (fp16 source, +softmax) + output projection.
// 32 pixels per block, 256 threads. Gather thread = (px, g, 8-ch half).
// ---------------------------------------------------------------------------
__global__ __launch_bounds__(256) void k4_dcn(const float* __restrict__ w_out,
                                              const float* __restrict__ b_out,
                                              float* __restrict__ out) {
    __shared__ float ws[64*64];
    __shared__ float msh[32*36];
    __shared__ float osh[32*72];
    __shared__ float dsh[32*65];

    const int px0 = blockIdx.x * 32;
    const int tid = threadIdx.x;

    for (int idx = tid; idx < 4096; idx += 256) ws[idx] = w_out[idx];
    for (int idx = tid; idx < 32*36; idx += 256) msh[idx] = g_mask[(size_t)px0*36 + idx];
    for (int idx = tid; idx < 32*72; idx += 256) osh[idx] = g_off[(size_t)px0*72 + idx];
    __syncthreads();

    // softmax over P per (pixel, group)
    if (tid < 128) {
        int p = tid >> 2, g = tid & 3;
        float* mp = &msh[p*36 + g*9];
        float mx = mp[0];
        #pragma unroll
        for (int q = 1; q < 9; ++q) mx = fmaxf(mx, mp[q]);
        float ssum = 0.f;
        #pragma unroll
        for (int q = 0; q < 9; ++q) { float e = expf(mp[q] - mx); mp[q] = e; ssum += e; }
        float r = 1.f / ssum;
        #pragma unroll
        for (int q = 0; q < 9; ++q) mp[q] *= r;
    }
    __syncthreads();

    // ---- deformable gather (fp16 source, fp32 accumulate) ----
    {
        const int pxl = tid >> 3;            // 0..31
        const int sub = tid & 7;
        const int g = sub >> 1, c8 = (sub & 1) * 8;
        const int px = px0 + pxl;
        const int n = px >> 16, h = (px >> 8) & 255, w = px & 255;

        float acc[8];
        #pragma unroll
        for (int j = 0; j < 8; ++j) acc[j] = 0.f;
        const float* mrow = &msh[pxl*36 + g*9];
        const float* orow = &osh[pxl*72 + g*18];
        const __half* xbase = g_xproj_h + (size_t)n*65536*64 + g*16 + c8;

        #pragma unroll
        for (int p = 0; p < 9; ++p) {
            float mwt = mrow[p];
            float ox = orow[p*2], oy = orow[p*2 + 1];
            float ix = (float)(w + p/3) + ox;
            float iy = (float)(h + p%3) + oy;
            float x0f = floorf(ix), y0f = floorf(iy);
            float fx = ix - x0f, fy = iy - y0f;
            int x0 = (int)x0f, y0 = (int)y0f;
            float w00 = (1.f - fy)*(1.f - fx)*mwt;
            float w01 = (1.f - fy)*fx*mwt;
            float w10 = fy*(1.f - fx)*mwt;
            float w11 = fy*fx*mwt;

            #pragma unroll
            for (int corner = 0; corner < 4; ++corner) {
                int yc = y0 + (corner >> 1);
                int xc = x0 + (corner & 1);
                float wgt = (corner == 0) ? w00 : (corner == 1) ? w01
                          : (corner == 2) ? w10 : w11;
                if (xc >= 1 && xc <= 256 && yc >= 1 && yc <= 256) {
                    const uint4 v = *(const uint4*)(xbase + ((size_t)(yc-1)*256 + (xc-1))*64);
                    float2 f0 = __half22float2(*(const __half2*)&v.x);
                    float2 f1 = __half22float2(*(const __half2*)&v.y);
                    float2 f2 = __half22float2(*(const __half2*)&v.z);
                    float2 f3 = __half22float2(*(const __half2*)&v.w);
                    acc[0] += wgt*f0.x; acc[1] += wgt*f0.y;
                    acc[2] += wgt*f1.x; acc[3] += wgt*f1.y;
                    acc[4] += wgt*f2.x; acc[5] += wgt*f2.y;
                    acc[6] += wgt*f3.x; acc[7] += wgt*f3.y;
                }
            }
        }
        float* dp = &dsh[pxl*65 + g*16 + c8];
        #pragma unroll
        for (int j = 0; j < 8; ++j) dp[j] = acc[j];
    }
    __syncthreads();

    // ---- output projection (f32x2) + NCHW store ----
    {
        const int pxl = tid & 31;
        const int ocg = tid >> 5;      // 8 groups of 8 oc
        const int oc0 = ocg * 8;
        float4 b1 = *(const float4*)&b_out[oc0];
        float4 b2 = *(const float4*)&b_out[oc0 + 4];
        u64 a0 = pk(b1.x, b1.y), a1 = pk(b1.z, b1.w);
        u64 a2 = pk(b2.x, b2.y), a3 = pk(b2.z, b2.w);
        for (int k = 0; k < 64; ++k) {
            u64 xv = pk2(dsh[pxl*65 + k]);
            const u64* wp = (const u64*)&ws[k*64 + oc0];
            fma2(a0, wp[0], xv);
            fma2(a1, wp[1], xv);
            fma2(a2, wp[2], xv);
            fma2(a3, wp[3], xv);
        }
        const int px = px0 + pxl;
        const int n = px >> 16, h = (px >> 8) & 255, w = px & 255;
        size_t ob = ((size_t)(n*64 + oc0)*256 + h)*256 + w;
        float r0, r1, r2, r3, r4, r5, r6, r7;
        upk(a0, r0, r1); upk(a1, r2, r3);
        upk(a2, r4, r5); upk(a3, r6, r7);
        out[ob]             = r0;
        out[ob + 1*65536]   = r1;
        out[ob + 2*65536]   = r2;
        out[ob + 3*65536]   = r3;
        out[ob + 4*65536]   = r4;
        out[ob + 5*65536]   = r5;
        out[ob + 6*65536]   = r6;
        out[ob + 7*65536]   = r7;
    }
}

// ---------------------------------------------------------------------------
extern "C" void kernel_launch(void* const* d_in, const int* in_sizes, int n_in,
                              void* d_out, int out_size) {
    const float* x      = (const float*)d_in[0];
    const float* conv_w = (const float*)d_in[1];
    const float* w_in   = (const float*)d_in[2];
    const float* b_in   = (const float*)d_in[3];
    const float* dw_w   = (const float*)d_in[4];
    const float* dw_b   = (const float*)d_in[5];
    const float* ln_g   = (const float*)d_in[6];
    const float* ln_b   = (const float*)d_in[7];
    const float* w_off  = (const float*)d_in[8];
    const float* b_off  = (const float*)d_in[9];
    const float* w_mask = (const float*)d_in[10];
    const float* b_mask = (const float*)d_in[11];
    const float* w_out  = (const float*)d_in[12];
    const float* b_out  = (const float*)d_in[13];
    float* out = (float*)d_out;

    k0_transpose<<<144, 256>>>(conv_w);
    dim3 g1(4, 256, 2);
    k1_conv<<<g1, 128>>>(x);
    k2_xproj<<<2048, 256>>>(w_in, b_in);
    k3a_x1<<<16384, 256>>>(dw_w, dw_b, ln_g, ln_b);
    k3b_offmask<<<2048, 256>>>(w_off, b_off, w_mask, b_mask);
    k4_dcn<<<4096, 256>>>(w_out, b_out, out);
}

// round 11
// speedup vs baseline: 2.2261x; 1.5725x over previous
#include <cuda_runtime.h>
#include <cuda_fp16.h>
#include <math.h>

// Problem constants
#define NB   2
#define HH   256
#define WW   256
#define CC   64
#define GG   4
#define PP   9
#define NPIX (NB*HH*WW)   // 131072

typedef unsigned long long u64;

// packed f32x2 helpers
__device__ __forceinline__ u64 pk2(float v) {
    u64 r; asm("mov.b64 %0, {%1, %1};" : "=l"(r) : "f"(v)); return r;
}
__device__ __forceinline__ u64 pk(float lo, float hi) {
    u64 r; asm("mov.b64 %0, {%1, %2};" : "=l"(r) : "f"(lo), "f"(hi)); return r;
}
__device__ __forceinline__ void upk(u64 v, float& lo, float& hi) {
    asm("mov.b64 {%0, %1}, %2;" : "=f"(lo), "=f"(hi) : "l"(v));
}
__device__ __forceinline__ void fma2(u64& d, u64 a, u64 b) {
    asm("fma.rn.f32x2 %0, %1, %2, %3;" : "=l"(d) : "l"(a), "l"(b), "l"(d));
}

// cp.async helpers
__device__ __forceinline__ unsigned smem_u32(const void* p) {
    return (unsigned)__cvta_generic_to_shared(p);
}
__device__ __forceinline__ void cp16(unsigned dst, const void* src) {
    asm volatile("cp.async.cg.shared.global [%0], [%1], 16;\n"
                 :: "r"(dst), "l"(src));
}
__device__ __forceinline__ void cp16p(unsigned dst, const void* src, bool ok) {
    int sz = ok ? 16 : 0;
    asm volatile("cp.async.cg.shared.global [%0], [%1], 16, %2;\n"
                 :: "r"(dst), "l"(src), "r"(sz));
}
#define CP_COMMIT asm volatile("cp.async.commit_group;\n" ::: "memory")
#define CP_WAIT1  asm volatile("cp.async.wait_group 1;\n" ::: "memory")

// tf32 helpers
__device__ __forceinline__ unsigned tf32r(float f) {
    unsigned u; asm("cvt.rna.tf32.f32 %0, %1;" : "=r"(u) : "f"(f)); return u;
}
__device__ __forceinline__ void mma_tf32(float* c, const unsigned* a,
                                         unsigned b0, unsigned b1) {
    asm volatile(
        "mma.sync.aligned.m16n8k8.row.col.f32.tf32.tf32.f32 "
        "{%0,%1,%2,%3}, {%4,%5,%6,%7}, {%8,%9}, {%0,%1,%2,%3};"
        : "+f"(c[0]), "+f"(c[1]), "+f"(c[2]), "+f"(c[3])
        : "r"(a[0]), "r"(a[1]), "r"(a[2]), "r"(a[3]), "r"(b0), "r"(b1));
}

// Scratch (device bss — no allocation at runtime)
__device__ float  g_y[NPIX*CC];        // conv+relu output, NHWC
__device__ __half g_xproj_h[NPIX*CC];  // input projection, NHWC, fp16 storage
__device__ float  g_x1[NPIX*CC];       // dwconv+LN+GELU, NHWC
__device__ float  g_off[NPIX*72];      // raw offsets (G*P*2)
__device__ float  g_mask[NPIX*36];     // mask logits (softmax applied in k4)
__device__ float  g_wT2[8*9*512];      // conv weights tf32-rounded: [chunk][tap][oc][ci8]

// ---------------------------------------------------------------------------
// K0: transpose + tf32-round conv weights (oc,ci,kh,kw) -> [chunk][tap][oc][ci8]
// ---------------------------------------------------------------------------
__global__ void k0_transpose(const float* __restrict__ w) {
    int i = blockIdx.x * blockDim.x + threadIdx.x;
    if (i < 64*64*9) {
        int oc  = i / 576;
        int ci  = (i / 9) % 64;
        int tap = i % 9;
        int chunk = ci >> 3, cil = ci & 7;
        g_wT2[((chunk*9 + tap)*64 + oc)*8 + cil] = __uint_as_float(tf32r(w[i]));
    }
}

// ---------------------------------------------------------------------------
// K1: stride-2 3x3 conv (64->64) + ReLU via tf32 mma.sync implicit GEMM.
// Block: 128 threads (4 warps) = 128 px x 64 oc. Warp: 32 px x 64 oc.
// K = 576 ordered tap-major: 8 chunks of 8 ci, 9 k-steps (one tap) each.
// Patch smem [ci8][ky][264 cols]; weights [tap][oc][ci8]. Double buffered.
// ---------------------------------------------------------------------------
#define K1_PATCH 6336            // 8 * 792 floats
#define K1_WT    4608            // 9 * 64 * 8 floats
#define K1_BUF   (K1_PATCH + K1_WT)
#define K1_SMEM  (2 * K1_BUF * 4)    // bytes = 87552

__global__ __launch_bounds__(128) void k1_conv(const float* __restrict__ x) {
    extern __shared__ float sm[];

    const int w0  = blockIdx.x * 128;       // 128 output cols per block
    const int h   = blockIdx.y;
    const int n   = blockIdx.z;
    const int tid = threadIdx.x;
    const int warp = tid >> 5, lane = tid & 31;
    const int gid = lane >> 2, tid4 = lane & 3;
    const int pxw = warp * 32;              // warp's local px base
    const int s_col = 2*w0 - 4;             // global col of patch col 0 (16B aligned)

    float c[2][8][4];
    #pragma unroll
    for (int ms = 0; ms < 2; ++ms)
        #pragma unroll
        for (int ns = 0; ns < 8; ++ns)
            #pragma unroll
            for (int j = 0; j < 4; ++j) c[ms][ns][j] = 0.f;

    auto prefetch = [&](int chunk, int buf) {
        unsigned spb = smem_u32(sm + buf*K1_BUF);
        unsigned wpb = smem_u32(sm + buf*K1_BUF + K1_PATCH);
        // patch: 8 ci x 3 ky x 66 cp16 (264 cols), zero-fill outside image
        for (int idx = tid; idx < 1584; idx += 128) {
            int ci = idx / 198;
            int r  = idx % 198;
            int ky = r / 66;
            int q  = r % 66;
            int row = 2*h - 1 + ky;
            int col = s_col + q*4;
            bool ok = ((unsigned)row < 512u) && ((unsigned)col <= 508u);
            const float* src = x + (ok ?
                ((size_t)(n*64 + chunk*8 + ci)*512 + row)*512 + col : 0);
            cp16p(spb + (unsigned)((ci*792 + ky*264 + q*4)*4), src, ok);
        }
        // weights: contiguous 4608-float slab
        const float* wsrc = g_wT2 + (size_t)chunk*K1_WT;
        for (int idx = tid; idx < 1152; idx += 128)
            cp16(wpb + (unsigned)(idx*16), wsrc + idx*4);
    };

    auto compute = [&](int buf) {
        const float* pp = sm + buf*K1_BUF;
        const float* wp = pp + K1_PATCH;
        // base offsets (floats); patch col for local px m at kx: 2m + kx + 3
        const int aB0 = tid4*792 + 2*(pxw + gid) + 3;     // ci=tid4
        const int aB1 = aB0 + 4*792;                      // ci=tid4+4
        const int bB  = gid*8 + tid4;                     // + tap*512 + ns*64
        #pragma unroll
        for (int tap = 0; tap < 9; ++tap) {
            const int ky = tap / 3, kx = tap % 3;
            const int toff = ky*264 + kx;
            unsigned a0[4], a1[4];
            // m-subtile 0: rows gid, gid+8  (cols +0 / +16)
            a0[0] = tf32r(pp[aB0 + toff]);
            a0[1] = tf32r(pp[aB0 + toff + 16]);
            a0[2] = tf32r(pp[aB1 + toff]);
            a0[3] = tf32r(pp[aB1 + toff + 16]);
            // m-subtile 1: rows gid+16, gid+24 (cols +32 / +48)
            a1[0] = tf32r(pp[aB0 + toff + 32]);
            a1[1] = tf32r(pp[aB0 + toff + 48]);
            a1[2] = tf32r(pp[aB1 + toff + 32]);
            a1[3] = tf32r(pp[aB1 + toff + 48]);
            #pragma unroll
            for (int ns = 0; ns < 8; ++ns) {
                unsigned b0 = __float_as_uint(wp[tap*512 + ns*64 + bB]);
                unsigned b1 = __float_as_uint(wp[tap*512 + ns*64 + bB + 4]);
                mma_tf32(c[0][ns], a0, b0, b1);
                mma_tf32(c[1][ns], a1, b0, b1);
            }
        }
    };

    prefetch(0, 0); CP_COMMIT;
    prefetch(1, 1); CP_COMMIT;
    for (int ch = 0; ch < 8; ++ch) {
        CP_WAIT1;
        __syncthreads();
        compute(ch & 1);
        __syncthreads();
        if (ch + 2 < 8) prefetch(ch + 2, ch & 1);
        CP_COMMIT;
    }

    // epilogue: ReLU + NHWC store (c rows: gid, gid+8 per m-subtile)
    const int pixbase = (n*256 + h)*256 + w0 + pxw;
    #pragma unroll
    for (int ms = 0; ms < 2; ++ms) {
        #pragma unroll
        for (int rr = 0; rr < 2; ++rr) {
            int m = pixbase + ms*16 + rr*8 + gid;
            float* dst = &g_y[(size_t)m*64 + tid4*2];
            #pragma unroll
            for (int ns = 0; ns < 8; ++ns) {
                float2 v;
                v.x = fmaxf(c[ms][ns][rr*2],     0.f);
                v.y = fmaxf(c[ms][ns][rr*2 + 1], 0.f);
                *(float2*)(dst + ns*8) = v;
            }
        }
    }
}

// ---------------------------------------------------------------------------
// K2: x_proj = y @ w_in + b_in  (64x64 GEMM per 64-pixel tile), f32x2 packed,
// fp16 output for the gather stage.
// ---------------------------------------------------------------------------
__global__ __launch_bounds__(256) void k2_xproj(const float* __restrict__ w_in,
                                                const float* __restrict__ b_in) {
    __shared__ float ys[64*65];
    __shared__ float ws[64*64];
    const int px0 = blockIdx.x * 64;
    const int tid = threadIdx.x;

    for (int idx = tid; idx < 4096; idx += 256) {
        int p = idx >> 6, k = idx & 63;
        ys[p*65 + k] = g_y[(size_t)px0*64 + idx];
        ws[idx]      = w_in[idx];
    }
    __syncthreads();

    const int ocg = tid & 15, pxg = tid >> 4;
    const int oc0 = ocg * 4, p0 = pxg * 4;
    float4 bv = *(const float4*)&b_in[oc0];
    u64 acc[4][2];
    #pragma unroll
    for (int i = 0; i < 4; ++i) { acc[i][0] = pk(bv.x, bv.y); acc[i][1] = pk(bv.z, bv.w); }

    for (int k = 0; k < 64; ++k) {
        const u64* wp = (const u64*)&ws[k*64 + oc0];
        u64 w0 = wp[0], w1 = wp[1];
        #pragma unroll
        for (int i = 0; i < 4; ++i) {
            u64 xv = pk2(ys[(p0 + i)*65 + k]);
            fma2(acc[i][0], w0, xv);
            fma2(acc[i][1], w1, xv);
        }
    }
    #pragma unroll
    for (int i = 0; i < 4; ++i) {
        float a, b, c, d;
        upk(acc[i][0], a, b); upk(acc[i][1], c, d);
        __half2 h0 = __floats2half2_rn(a, b);
        __half2 h1 = __floats2half2_rn(c, d);
        uint2 o;
        o.x = *(unsigned*)&h0; o.y = *(unsigned*)&h1;
        *(uint2*)&g_xproj_h[(size_t)(px0 + p0 + i)*64 + oc0] = o;
    }
}

// ---------------------------------------------------------------------------
// K3a: x1 = GELU(LayerNorm(dwconv3x3(y) + dw_b))    (one warp per pixel)
// ---------------------------------------------------------------------------
__global__ __launch_bounds__(256) void k3a_x1(const float* __restrict__ dw_w,
                                              const float* __restrict__ dw_b,
                                              const float* __restrict__ ln_g,
                                              const float* __restrict__ ln_b) {
    const int warp = threadIdx.x >> 5, lane = threadIdx.x & 31;
    const int px = blockIdx.x * 8 + warp;
    const int n = px >> 16, h = (px >> 8) & 255, w = px & 255;

    float v0 = dw_b[lane], v1 = dw_b[lane + 32];
    #pragma unroll
    for (int ky = 0; ky < 3; ++ky) {
        int hh = h + ky - 1;
        if (hh < 0 || hh >= 256) continue;
        #pragma unroll
        for (int kx = 0; kx < 3; ++kx) {
            int wc = w + kx - 1;
            if (wc < 0 || wc >= 256) continue;
            const float* yp = &g_y[(size_t)((n*256 + hh)*256 + wc)*64];
            int tap = ky*3 + kx;
            v0 += yp[lane]      * dw_w[tap*64 + lane];
            v1 += yp[lane + 32] * dw_w[tap*64 + lane + 32];
        }
    }
    float s  = v0 + v1;
    float sq = v0*v0 + v1*v1;
    #pragma unroll
    for (int o = 16; o > 0; o >>= 1) {
        s  += __shfl_xor_sync(0xFFFFFFFFu, s,  o);
        sq += __shfl_xor_sync(0xFFFFFFFFu, sq, o);
    }
    float m   = s * (1.f/64.f);
    float var = sq * (1.f/64.f) - m*m;
    float inv = rsqrtf(var + 1e-5f);

    {
        float t = (v0 - m)*inv*ln_g[lane] + ln_b[lane];
        g_x1[(size_t)px*64 + lane] = t * normcdff(t);
        float u = (v1 - m)*inv*ln_g[lane + 32] + ln_b[lane + 32];
        g_x1[(size_t)px*64 + lane + 32] = u * normcdff(u);
    }
}

// ---------------------------------------------------------------------------
// K3b: offset = x1 @ w_off + b_off ; mask_logits = x1 @ w_mask + b_mask
// Combined 64x112 GEMM, f32x2 packed.
// ---------------------------------------------------------------------------
__global__ __launch_bounds__(256) void k3b_offmask(const float* __restrict__ w_off,
                                                   const float* __restrict__ b_off,
                                                   const float* __restrict__ w_mask,
                                                   const float* __restrict__ b_mask) {
    __shared__ float xs[64*65];
    __shared__ float ws[64*112];
    const int px0 = blockIdx.x * 64;
    const int tid = threadIdx.x;

    for (int idx = tid; idx < 4096; idx += 256) {
        int p = idx >> 6, k = idx & 63;
        xs[p*65 + k] = g_x1[(size_t)px0*64 + idx];
    }
    for (int idx = tid; idx < 64*112; idx += 256) {
        int k = idx / 112, oc = idx % 112;
        float v = 0.f;
        if (oc < 72)       v = w_off[k*72 + oc];
        else if (oc < 108) v = w_mask[k*36 + oc - 72];
        ws[idx] = v;
    }
    __syncthreads();

    const int ocg = tid & 15, pxg = tid >> 4;
    const int p0 = pxg * 4;

    for (int half = 0; half < 2; ++half) {
        int oc0 = ocg*4 + half*64;
        if (oc0 >= 112) break;
        u64 acc[4][2];
        {
            float bb[4];
            #pragma unroll
            for (int j = 0; j < 4; ++j) {
                int oc = oc0 + j;
                bb[j] = (oc < 72) ? b_off[oc] : ((oc < 108) ? b_mask[oc - 72] : 0.f);
            }
            #pragma unroll
            for (int i = 0; i < 4; ++i) { acc[i][0] = pk(bb[0], bb[1]); acc[i][1] = pk(bb[2], bb[3]); }
        }
        for (int k = 0; k < 64; ++k) {
            const u64* wp = (const u64*)&ws[k*112 + oc0];
            u64 w0 = wp[0], w1 = wp[1];
            #pragma unroll
            for (int i = 0; i < 4; ++i) {
                u64 xv = pk2(xs[(p0 + i)*65 + k]);
                fma2(acc[i][0], w0, xv);
                fma2(acc[i][1], w1, xv);
            }
        }
        #pragma unroll
        for (int i = 0; i < 4; ++i) {
            int px = px0 + p0 + i;
            float v01[2], v23[2];
            upk(acc[i][0], v01[0], v01[1]);
            upk(acc[i][1], v23[0], v23[1]);
            #pragma unroll
            for (int j = 0; j < 4; ++j) {
                int oc = oc0 + j;
                float v = (j < 2) ? v01[j] : v23[j - 2];
                if (oc < 72)       g_off[(size_t)px*72 + oc]       = v;
                else if (oc < 108) g_mask[(size_t)px*36 + oc - 72] = v;
            }
        }
    }
}

// ---------------------------------------------------------------------------
// K4: DCNv3 bilinear gather (fp16 source, +softmax) + output projection.
// 32 pixels per block, 256 threads. Gather thread = (px, g, 8-ch half).
// ---------------------------------------------------------------------------
__global__ __launch_bounds__(256) void k4_dcn(const float* __restrict__ w_out,
                                              const float* __restrict__ b_out,
                                              float* __restrict__ out) {
    __shared__ float ws[64*64];
    __shared__ float msh[32*36];
    __shared__ float osh[32*72];
    __shared__ float dsh[32*65];

    const int px0 = blockIdx.x * 32;
    const int tid = threadIdx.x;

    for (int idx = tid; idx < 4096; idx += 256) ws[idx] = w_out[idx];
    for (int idx = tid; idx < 32*36; idx += 256) msh[idx] = g_mask[(size_t)px0*36 + idx];
    for (int idx = tid; idx < 32*72; idx += 256) osh[idx] = g_off[(size_t)px0*72 + idx];
    __syncthreads();

    // softmax over P per (pixel, group)
    if (tid < 128) {
        int p = tid >> 2, g = tid & 3;
        float* mp = &msh[p*36 + g*9];
        float mx = mp[0];
        #pragma unroll
        for (int q = 1; q < 9; ++q) mx = fmaxf(mx, mp[q]);
        float ssum = 0.f;
        #pragma unroll
        for (int q = 0; q < 9; ++q) { float e = expf(mp[q] - mx); mp[q] = e; ssum += e; }
        float r = 1.f / ssum;
        #pragma unroll
        for (int q = 0; q < 9; ++q) mp[q] *= r;
    }
    __syncthreads();

    // ---- deformable gather (fp16 source, fp32 accumulate) ----
    {
        const int pxl = tid >> 3;            // 0..31
        const int sub = tid & 7;
        const int g = sub >> 1, c8 = (sub & 1) * 8;
        const int px = px0 + pxl;
        const int n = px >> 16, h = (px >> 8) & 255, w = px & 255;

        float acc[8];
        #pragma unroll
        for (int j = 0; j < 8; ++j) acc[j] = 0.f;
        const float* mrow = &msh[pxl*36 + g*9];
        const float* orow = &osh[pxl*72 + g*18];
        const __half* xbase = g_xproj_h + (size_t)n*65536*64 + g*16 + c8;

        #pragma unroll
        for (int p = 0; p < 9; ++p) {
            float mwt = mrow[p];
            float ox = orow[p*2], oy = orow[p*2 + 1];
            float ix = (float)(w + p/3) + ox;
            float iy = (float)(h + p%3) + oy;
            float x0f = floorf(ix), y0f = floorf(iy);
            float fx = ix - x0f, fy = iy - y0f;
            int x0 = (int)x0f, y0 = (int)y0f;
            float w00 = (1.f - fy)*(1.f - fx)*mwt;
            float w01 = (1.f - fy)*fx*mwt;
            float w10 = fy*(1.f - fx)*mwt;
            float w11 = fy*fx*mwt;

            #pragma unroll
            for (int corner = 0; corner < 4; ++corner) {
                int yc = y0 + (corner >> 1);
                int xc = x0 + (corner & 1);
                float wgt = (corner == 0) ? w00 : (corner == 1) ? w01
                          : (corner == 2) ? w10 : w11;
                if (xc >= 1 && xc <= 256 && yc >= 1 && yc <= 256) {
                    const uint4 v = *(const uint4*)(xbase + ((size_t)(yc-1)*256 + (xc-1))*64);
                    float2 f0 = __half22float2(*(const __half2*)&v.x);
                    float2 f1 = __half22float2(*(const __half2*)&v.y);
                    float2 f2 = __half22float2(*(const __half2*)&v.z);
                    float2 f3 = __half22float2(*(const __half2*)&v.w);
                    acc[0] += wgt*f0.x; acc[1] += wgt*f0.y;
                    acc[2] += wgt*f1.x; acc[3] += wgt*f1.y;
                    acc[4] += wgt*f2.x; acc[5] += wgt*f2.y;
                    acc[6] += wgt*f3.x; acc[7] += wgt*f3.y;
                }
            }
        }
        float* dp = &dsh[pxl*65 + g*16 + c8];
        #pragma unroll
        for (int j = 0; j < 8; ++j) dp[j] = acc[j];
    }
    __syncthreads();

    // ---- output projection (f32x2) + NCHW store ----
    {
        const int pxl = tid & 31;
        const int ocg = tid >> 5;      // 8 groups of 8 oc
        const int oc0 = ocg * 8;
        float4 b1 = *(const float4*)&b_out[oc0];
        float4 b2 = *(const float4*)&b_out[oc0 + 4];
        u64 a0 = pk(b1.x, b1.y), a1 = pk(b1.z, b1.w);
        u64 a2 = pk(b2.x, b2.y), a3 = pk(b2.z, b2.w);
        for (int k = 0; k < 64; ++k) {
            u64 xv = pk2(dsh[pxl*65 + k]);
            const u64* wp = (const u64*)&ws[k*64 + oc0];
            fma2(a0, wp[0], xv);
            fma2(a1, wp[1], xv);
            fma2(a2, wp[2], xv);
            fma2(a3, wp[3], xv);
        }
        const int px = px0 + pxl;
        const int n = px >> 16, h = (px >> 8) & 255, w = px & 255;
        size_t ob = ((size_t)(n*64 + oc0)*256 + h)*256 + w;
        float r0, r1, r2, r3, r4, r5, r6, r7;
        upk(a0, r0, r1); upk(a1, r2, r3);
        upk(a2, r4, r5); upk(a3, r6, r7);
        out[ob]             = r0;
        out[ob + 1*65536]   = r1;
        out[ob + 2*65536]   = r2;
        out[ob + 3*65536]   = r3;
        out[ob + 4*65536]   = r4;
        out[ob + 5*65536]   = r5;
        out[ob + 6*65536]   = r6;
        out[ob + 7*65536]   = r7;
    }
}

// ---------------------------------------------------------------------------
extern "C" void kernel_launch(void* const* d_in, const int* in_sizes, int n_in,
                              void* d_out, int out_size) {
    const float* x      = (const float*)d_in[0];
    const float* conv_w = (const float*)d_in[1];
    const float* w_in   = (const float*)d_in[2];
    const float* b_in   = (const float*)d_in[3];
    const float* dw_w   = (const float*)d_in[4];
    const float* dw_b   = (const float*)d_in[5];
    const float* ln_g   = (const float*)d_in[6];
    const float* ln_b   = (const float*)d_in[7];
    const float* w_off  = (const float*)d_in[8];
    const float* b_off  = (const float*)d_in[9];
    const float* w_mask = (const float*)d_in[10];
    const float* b_mask = (const float*)d_in[11];
    const float* w_out  = (const float*)d_in[12];
    const float* b_out  = (const float*)d_in[13];
    float* out = (float*)d_out;

    cudaFuncSetAttribute(k1_conv, cudaFuncAttributeMaxDynamicSharedMemorySize, K1_SMEM);

    k0_transpose<<<144, 256>>>(conv_w);
    dim3 g1(2, 256, 2);
    k1_conv<<<g1, 128, K1_SMEM>>>(x);
    k2_xproj<<<2048, 256>>>(w_in, b_in);
    k3a_x1<<<16384, 256>>>(dw_w, dw_b, ln_g, ln_b);
    k3b_offmask<<<2048, 256>>>(w_off, b_off, w_mask, b_mask);
    k4_dcn<<<4096, 256>>>(w_out, b_out, out);
}